// round 1
// baseline (speedup 1.0000x reference)
#include <cuda_runtime.h>

#define BB 4
#define NN 160
#define DD 64
#define ZIc 64
#define ZEc 64
#define LL 4
#define LEc 8
#define H1 128
#define H2 64

// Scratch (allocation-free: __device__ globals)
__device__ float g_piA[BB * NN * H1];  // pi + pz + bi1 folded
__device__ float g_pjA[BB * NN * H1];
__device__ float g_qiA[BB * NN * H1];  // qi + qz + bl1 folded
__device__ float g_qjA[BB * NN * H1];
__device__ float g_qlA[LL * H1];

// ---------------------------------------------------------------------------
// Kernel 1: per-(b,n) projections, all four 64->128 GEMVs + folded z terms
// grid = B*N blocks, 128 threads (thread = output channel k)
// ---------------------------------------------------------------------------
__global__ void proj_kernel(const float* __restrict__ ne,
                            const float* __restrict__ zi,
                            const float* __restrict__ ze,
                            const float* __restrict__ lag,
                            const float* __restrict__ Wi1,
                            const float* __restrict__ bi1,
                            const float* __restrict__ Wl1,
                            const float* __restrict__ bl1)
{
    __shared__ float s_ne[DD], s_zi[ZIc], s_ze[ZEc];
    const int bid = blockIdx.x;      // b*NN + n
    const int b   = bid / NN;
    const int k   = threadIdx.x;     // 0..127

    if (k < DD)  s_ne[k] = ne[bid * DD + k];
    if (k < ZIc) s_zi[k] = zi[b * ZIc + k];
    if (k < ZEc) s_ze[k] = ze[b * ZEc + k];
    __syncthreads();

    float api = bi1[k];
    float apj = 0.f;
    float aqi = bl1[k];
    float aqj = 0.f;

    #pragma unroll 8
    for (int d = 0; d < DD; d++) {
        const float nd = s_ne[d];
        api += nd * Wi1[d * H1 + k];
        apj += nd * Wi1[(DD + d) * H1 + k];
        aqi += nd * Wl1[d * H1 + k];
        aqj += nd * Wl1[(DD + d) * H1 + k];
    }
    #pragma unroll 8
    for (int z = 0; z < ZIc; z++) {
        api += s_zi[z] * Wi1[(2 * DD + z) * H1 + k];
        aqi += s_ze[z] * Wl1[(2 * DD + z) * H1 + k];
    }

    g_piA[bid * H1 + k] = api;
    g_pjA[bid * H1 + k] = apj;
    g_qiA[bid * H1 + k] = aqi;
    g_qjA[bid * H1 + k] = aqj;

    if (bid == 0) {
        #pragma unroll
        for (int l = 0; l < LL; l++) {
            float a = 0.f;
            #pragma unroll
            for (int e = 0; e < LEc; e++)
                a += lag[l * LEc + e] * Wl1[(2 * DD + ZEc + e) * H1 + k];
            g_qlA[l * H1 + k] = a;
        }
    }
}

// ---------------------------------------------------------------------------
// Kernel 2: pairwise 128->64->1 MLP + sigmoid + mask.
// grid = B*(N/4) intra blocks + B*L*(N/4) inter blocks = 800
// block = 160 threads; thread = j; block loops over 4 consecutive i.
// smem: pjT[k][j] (conflict-free per-lane), W2 copy (broadcast float4 reads),
//       u[k] (pi_i [+ ql_l] folded vector, broadcast reads).
// ---------------------------------------------------------------------------
extern __shared__ float smem[];

__global__ __launch_bounds__(160) void pair_kernel(
    const float* __restrict__ Wi2, const float* __restrict__ bi2,
    const float* __restrict__ Wi3, const float* __restrict__ bi3,
    const float* __restrict__ Wl2, const float* __restrict__ bl2,
    const float* __restrict__ Wl3, const float* __restrict__ bl3,
    float* __restrict__ out)
{
    float* s_pjT = smem;                  // H1*NN = 20480 floats
    float* s_W2  = s_pjT + H1 * NN;       // 8192 floats
    float* s_u   = s_W2 + H1 * H2;        // 128
    float* s_b2  = s_u + H1;              // 64
    float* s_W3  = s_b2 + H2;             // 64

    const int tid = threadIdx.x;
    const int bid = blockIdx.x;

    const bool intra = (bid < BB * (NN / 4));
    int b, l = 0, i0;
    const float *gu, *gv, *W2, *b2, *W3;
    float b3;
    if (intra) {
        b  = bid / (NN / 4);
        i0 = (bid % (NN / 4)) * 4;
        gu = g_piA; gv = g_pjA; W2 = Wi2; b2 = bi2; W3 = Wi3; b3 = bi3[0];
    } else {
        const int e = bid - BB * (NN / 4);
        b = e / (LL * (NN / 4));
        const int r = e % (LL * (NN / 4));
        l  = r / (NN / 4);
        i0 = (r % (NN / 4)) * 4;
        gu = g_qiA; gv = g_qjA; W2 = Wl2; b2 = bl2; W3 = Wl3; b3 = bl3[0];
    }

    // Load pj (this b) transposed into smem: s_pjT[k*NN + j]
    const float* pvb = gv + b * NN * H1;
    for (int idx = tid; idx < NN * H1; idx += 160) {
        const int j = idx >> 7;        // idx / 128
        const int k = idx & (H1 - 1);  // idx % 128
        s_pjT[k * NN + j] = pvb[idx];
    }
    for (int idx = tid; idx < H1 * H2; idx += 160) s_W2[idx] = W2[idx];
    if (tid < H2) { s_b2[tid] = b2[tid]; s_W3[tid] = W3[tid]; }
    __syncthreads();

    const int j = tid;   // 160 threads, all valid

    for (int ii = 0; ii < 4; ii++) {
        const int i = i0 + ii;
        if (ii) __syncthreads();
        // u[k] = pi'(b,i,k) [+ ql(l,k) for inter]
        for (int k = tid; k < H1; k += 160) {
            float u = gu[(b * NN + i) * H1 + k];
            if (!intra) u += g_qlA[l * H1 + k];
            s_u[k] = u;
        }
        __syncthreads();

        float acc[H2];
        #pragma unroll
        for (int m = 0; m < H2; m++) acc[m] = s_b2[m];

        #pragma unroll 2
        for (int k = 0; k < H1; k++) {
            float hk = s_u[k] + s_pjT[k * NN + j];
            hk = fmaxf(hk, 0.f);
            const float4* w4 = (const float4*)(s_W2 + k * H2);
            #pragma unroll
            for (int m4 = 0; m4 < H2 / 4; m4++) {
                const float4 w = w4[m4];
                acc[4 * m4 + 0] += hk * w.x;
                acc[4 * m4 + 1] += hk * w.y;
                acc[4 * m4 + 2] += hk * w.z;
                acc[4 * m4 + 3] += hk * w.w;
            }
        }

        float logit = b3;
        #pragma unroll
        for (int m = 0; m < H2; m++)
            logit += fmaxf(acc[m], 0.f) * s_W3[m];

        float sig = 1.f / (1.f + __expf(-logit));
        if (i == j) sig = 0.f;

        size_t off;
        if (intra)
            off = ((size_t)(b * NN + i)) * NN + j;
        else
            off = (size_t)BB * NN * NN +
                  ((size_t)((b * LL + l) * NN) + i) * NN + j;
        out[off] = sig;
    }
}

static const int PAIR_SMEM_BYTES = (H1 * NN + H1 * H2 + H1 + H2 + H2) * (int)sizeof(float);

extern "C" void kernel_launch(void* const* d_in, const int* in_sizes, int n_in,
                              void* d_out, int out_size)
{
    const float* ne  = (const float*)d_in[0];
    const float* zi  = (const float*)d_in[1];
    const float* ze  = (const float*)d_in[2];
    const float* lag = (const float*)d_in[3];
    const float* Wi1 = (const float*)d_in[4];
    const float* bi1 = (const float*)d_in[5];
    const float* Wi2 = (const float*)d_in[6];
    const float* bi2 = (const float*)d_in[7];
    const float* Wi3 = (const float*)d_in[8];
    const float* bi3 = (const float*)d_in[9];
    const float* Wl1 = (const float*)d_in[10];
    const float* bl1 = (const float*)d_in[11];
    const float* Wl2 = (const float*)d_in[12];
    const float* bl2 = (const float*)d_in[13];
    const float* Wl3 = (const float*)d_in[14];
    const float* bl3 = (const float*)d_in[15];
    float* out = (float*)d_out;

    cudaFuncSetAttribute(pair_kernel,
                         cudaFuncAttributeMaxDynamicSharedMemorySize,
                         PAIR_SMEM_BYTES);

    proj_kernel<<<BB * NN, H1>>>(ne, zi, ze, lag, Wi1, bi1, Wl1, bl1);

    const int nblocks = BB * (NN / 4) + BB * LL * (NN / 4);  // 160 + 640 = 800
    pair_kernel<<<nblocks, 160, PAIR_SMEM_BYTES>>>(
        Wi2, bi2, Wi3, bi3, Wl2, bl2, Wl3, bl3, out);
}

// round 2
// speedup vs baseline: 1.6739x; 1.6739x over previous
#include <cuda_runtime.h>

#define BB 4
#define NN 160
#define DD 64
#define ZIc 64
#define ZEc 64
#define LL 4
#define LEc 8
#define H1 128
#define H2 64
#define NP 164   // padded pjT row stride (16B-aligned rows, 4-way STS conflict max)

// Scratch (allocation-free: __device__ globals)
__device__ float g_piA[BB * NN * H1];  // pi + pz + bi1 folded
__device__ float g_pjA[BB * NN * H1];
__device__ float g_qiA[BB * NN * H1];  // qi + qz + bl1 folded
__device__ float g_qjA[BB * NN * H1];
__device__ float g_qlA[LL * H1];

// ---------------------------------------------------------------------------
// Kernel 1: per-(b,n) projections (tiny; ~6us total)
// ---------------------------------------------------------------------------
__global__ void proj_kernel(const float* __restrict__ ne,
                            const float* __restrict__ zi,
                            const float* __restrict__ ze,
                            const float* __restrict__ lag,
                            const float* __restrict__ Wi1,
                            const float* __restrict__ bi1,
                            const float* __restrict__ Wl1,
                            const float* __restrict__ bl1)
{
    __shared__ float s_ne[DD], s_zi[ZIc], s_ze[ZEc];
    const int bid = blockIdx.x;      // b*NN + n
    const int b   = bid / NN;
    const int k   = threadIdx.x;     // 0..127

    if (k < DD)  s_ne[k] = ne[bid * DD + k];
    if (k < ZIc) s_zi[k] = zi[b * ZIc + k];
    if (k < ZEc) s_ze[k] = ze[b * ZEc + k];
    __syncthreads();

    float api = bi1[k];
    float apj = 0.f;
    float aqi = bl1[k];
    float aqj = 0.f;

    #pragma unroll 8
    for (int d = 0; d < DD; d++) {
        const float nd = s_ne[d];
        api += nd * Wi1[d * H1 + k];
        apj += nd * Wi1[(DD + d) * H1 + k];
        aqi += nd * Wl1[d * H1 + k];
        aqj += nd * Wl1[(DD + d) * H1 + k];
    }
    #pragma unroll 8
    for (int z = 0; z < ZIc; z++) {
        api += s_zi[z] * Wi1[(2 * DD + z) * H1 + k];
        aqi += s_ze[z] * Wl1[(2 * DD + z) * H1 + k];
    }

    g_piA[bid * H1 + k] = api;
    g_pjA[bid * H1 + k] = apj;
    g_qiA[bid * H1 + k] = aqi;
    g_qjA[bid * H1 + k] = aqj;

    if (bid == 0) {
        #pragma unroll
        for (int l = 0; l < LL; l++) {
            float a = 0.f;
            #pragma unroll
            for (int e = 0; e < LEc; e++)
                a += lag[l * LEc + e] * Wl1[(2 * DD + ZEc + e) * H1 + k];
            g_qlA[l * H1 + k] = a;
        }
    }
}

// ---------------------------------------------------------------------------
// Kernel 2: pairwise 128->64->1 MLP, register-tiled 8j x 8m, f32x2 FMAs.
// 800 blocks x 320 threads. Block = 4 i's (2 at a time), one (b,[l]).
// thread = (i2, jt, mt): 8 j's (jt*8..+7) x 8 m's (mt*8..+7), acc packed m-pairs.
// smem: pjT[k][j] (padded stride NP) + u[2][128]. W2 read via LDG (L1-hot).
// ---------------------------------------------------------------------------
extern __shared__ float smem[];

__global__ __launch_bounds__(320, 2) void pair_kernel(
    const float* __restrict__ Wi2, const float* __restrict__ bi2,
    const float* __restrict__ Wi3, const float* __restrict__ bi3,
    const float* __restrict__ Wl2, const float* __restrict__ bl2,
    const float* __restrict__ Wl3, const float* __restrict__ bl3,
    float* __restrict__ out)
{
    float* s_pjT = smem;                  // H1 * NP floats
    float* s_u   = s_pjT + H1 * NP;       // 2 * H1

    const int tid = threadIdx.x;
    const int bid = blockIdx.x;

    const bool intra = (bid < BB * (NN / 4));
    int b, l = 0, i0;
    const float *gu, *gv, *W2, *b2, *W3, *b3p;
    if (intra) {
        b  = bid / (NN / 4);
        i0 = (bid % (NN / 4)) * 4;
        gu = g_piA; gv = g_pjA; W2 = Wi2; b2 = bi2; W3 = Wi3; b3p = bi3;
    } else {
        const int e = bid - BB * (NN / 4);
        b = e / (LL * (NN / 4));
        const int r = e % (LL * (NN / 4));
        l  = r / (NN / 4);
        i0 = (r % (NN / 4)) * 4;
        gu = g_qiA; gv = g_qjA; W2 = Wl2; b2 = bl2; W3 = Wl3; b3p = bl3;
    }

    // Load pj (this b) transposed into smem: s_pjT[k*NP + j]
    const float* pvb = gv + b * NN * H1;
    for (int idx = tid; idx < NN * H1; idx += 320) {
        const int j = idx >> 7;        // idx / 128
        const int k = idx & (H1 - 1);  // idx % 128
        s_pjT[k * NP + j] = pvb[idx];
    }
    __syncthreads();

    const int i2 = tid / 160;
    const int rr = tid % 160;
    const int jt = rr >> 3;       // 0..19
    const int mt = rr & 7;        // 0..7
    const int j0 = jt * 8;
    const int m0 = mt * 8;

    for (int ii = 0; ii < 2; ii++) {
        if (ii) __syncthreads();
        // u[i2][k] = pi'(b,i,k) [+ ql(l,k) for inter]
        for (int k = tid; k < 2 * H1; k += 320) {
            const int kk = k & (H1 - 1);
            const int ki = k >> 7;
            float u = gu[(b * NN + (i0 + ii * 2 + ki)) * H1 + kk];
            if (!intra) u += g_qlA[l * H1 + kk];
            s_u[k] = u;
        }
        __syncthreads();

        const int i = i0 + ii * 2 + i2;
        const float* su = s_u + i2 * H1;

        // init acc with b2 (packed pairs)
        unsigned long long acc[8][4];
        {
            const unsigned long long* b2p =
                (const unsigned long long*)(b2 + m0);
            #pragma unroll
            for (int mp = 0; mp < 4; mp++) {
                const unsigned long long bv = b2p[mp];
                #pragma unroll
                for (int jj = 0; jj < 8; jj++) acc[jj][mp] = bv;
            }
        }

        const float* w2k = W2 + m0;
        #pragma unroll 4
        for (int k = 0; k < H1; k++) {
            const float u = su[k];
            const float4 p0 = *(const float4*)(s_pjT + k * NP + j0);
            const float4 p1 = *(const float4*)(s_pjT + k * NP + j0 + 4);
            float h[8];
            h[0] = fmaxf(u + p0.x, 0.f);
            h[1] = fmaxf(u + p0.y, 0.f);
            h[2] = fmaxf(u + p0.z, 0.f);
            h[3] = fmaxf(u + p0.w, 0.f);
            h[4] = fmaxf(u + p1.x, 0.f);
            h[5] = fmaxf(u + p1.y, 0.f);
            h[6] = fmaxf(u + p1.z, 0.f);
            h[7] = fmaxf(u + p1.w, 0.f);

            const ulonglong2 wa = *(const ulonglong2*)(w2k);
            const ulonglong2 wb = *(const ulonglong2*)(w2k + 4);
            w2k += H2;

            #pragma unroll
            for (int jj = 0; jj < 8; jj++) {
                unsigned long long hh;
                asm("mov.b64 %0, {%1, %1};" : "=l"(hh) : "f"(h[jj]));
                asm("fma.rn.f32x2 %0, %1, %2, %0;"
                    : "+l"(acc[jj][0]) : "l"(hh), "l"(wa.x));
                asm("fma.rn.f32x2 %0, %1, %2, %0;"
                    : "+l"(acc[jj][1]) : "l"(hh), "l"(wa.y));
                asm("fma.rn.f32x2 %0, %1, %2, %0;"
                    : "+l"(acc[jj][2]) : "l"(hh), "l"(wb.x));
                asm("fma.rn.f32x2 %0, %1, %2, %0;"
                    : "+l"(acc[jj][3]) : "l"(hh), "l"(wb.y));
            }
        }

        // epilogue: relu(acc) . W3, reduce across 8 mt-lanes, sigmoid, store
        float w3r[8];
        #pragma unroll
        for (int t = 0; t < 8; t++) w3r[t] = W3[m0 + t];

        float part[8];
        #pragma unroll
        for (int jj = 0; jj < 8; jj++) {
            float lg = 0.f;
            #pragma unroll
            for (int mp = 0; mp < 4; mp++) {
                const float c0 = __uint_as_float((unsigned)acc[jj][mp]);
                const float c1 = __uint_as_float((unsigned)(acc[jj][mp] >> 32));
                lg += fmaxf(c0, 0.f) * w3r[2 * mp];
                lg += fmaxf(c1, 0.f) * w3r[2 * mp + 1];
            }
            part[jj] = lg;
        }
        #pragma unroll
        for (int jj = 0; jj < 8; jj++) {
            part[jj] += __shfl_xor_sync(0xFFFFFFFFu, part[jj], 1, 32);
            part[jj] += __shfl_xor_sync(0xFFFFFFFFu, part[jj], 2, 32);
            part[jj] += __shfl_xor_sync(0xFFFFFFFFu, part[jj], 4, 32);
        }

        float lg = part[0];
        #pragma unroll
        for (int jj = 1; jj < 8; jj++)
            if (mt == jj) lg = part[jj];
        lg += b3p[0];

        float sig = 1.f / (1.f + __expf(-lg));
        const int j = j0 + mt;
        if (i == j) sig = 0.f;

        size_t off;
        if (intra)
            off = ((size_t)(b * NN + i)) * NN + j;
        else
            off = (size_t)BB * NN * NN +
                  ((size_t)((b * LL + l) * NN) + i) * NN + j;
        out[off] = sig;
    }
}

static const int PAIR_SMEM_BYTES = (H1 * NP + 2 * H1) * (int)sizeof(float);

extern "C" void kernel_launch(void* const* d_in, const int* in_sizes, int n_in,
                              void* d_out, int out_size)
{
    const float* ne  = (const float*)d_in[0];
    const float* zi  = (const float*)d_in[1];
    const float* ze  = (const float*)d_in[2];
    const float* lag = (const float*)d_in[3];
    const float* Wi1 = (const float*)d_in[4];
    const float* bi1 = (const float*)d_in[5];
    const float* Wi2 = (const float*)d_in[6];
    const float* bi2 = (const float*)d_in[7];
    const float* Wi3 = (const float*)d_in[8];
    const float* bi3 = (const float*)d_in[9];
    const float* Wl1 = (const float*)d_in[10];
    const float* bl1 = (const float*)d_in[11];
    const float* Wl2 = (const float*)d_in[12];
    const float* bl2 = (const float*)d_in[13];
    const float* Wl3 = (const float*)d_in[14];
    const float* bl3 = (const float*)d_in[15];
    float* out = (float*)d_out;

    cudaFuncSetAttribute(pair_kernel,
                         cudaFuncAttributeMaxDynamicSharedMemorySize,
                         PAIR_SMEM_BYTES);

    proj_kernel<<<BB * NN, H1>>>(ne, zi, ze, lag, Wi1, bi1, Wl1, bl1);

    const int nblocks = BB * (NN / 4) + BB * LL * (NN / 4);  // 160 + 640 = 800
    pair_kernel<<<nblocks, 320, PAIR_SMEM_BYTES>>>(
        Wi2, bi2, Wi3, bi3, Wl2, bl2, Wl3, bl3, out);
}